// round 15
// baseline (speedup 1.0000x reference)
#include <cuda_runtime.h>
#include <cstdint>
#include <cstdio>

#define B_    64
#define T_    256
#define E_    256
#define H_    512
#define H4_   2048
#define TAGS_ 50

#define GP_J  68                         // split-K partial col stride (reduce CF)
#define PRE_S 20                         // pre-GEMM smem row stride (floats)
// lstm smem: sW 512*32 + sH 512*64 + lens
#define LSTM_SMEM_FLOATS (512 * 32 + 512 * 64 + 64)
#define LSTM_SMEM_BYTES  (LSTM_SMEM_FLOATS * 4)

// rounded-weight scratch offsets (floats)
#define WR_F1 0
#define WR_B1 (2048 * 256)
#define WR_F2 (2 * 2048 * 256)
#define WR_B2 (2 * 2048 * 256 + 2048 * 1024)
#define WR_TOTAL (2 * 2048 * 256 + 2 * 2048 * 1024)

// ---------------- scratch ----------------------------------------------------
__device__ float g_e[B_ * T_ * E_];
__device__ float g_preF[(size_t)B_ * T_ * H4_];
__device__ float g_preB[(size_t)B_ * T_ * H4_];
__device__ float g_out1[(size_t)B_ * T_ * 2 * H_];
__device__ float g_out2[(size_t)B_ * T_ * 2 * H_];
__device__ float g_hF[2][H_ * B_];          // transposed: [k][row], tf32-rounded
__device__ float g_hB[2][H_ * B_];
__device__ float g_wrnd[WR_TOTAL];          // RNA-rounded w_ih weights
__device__ __align__(128) unsigned g_barF;
__device__ __align__(128) unsigned g_barB;
__device__ int g_is64;
__device__ int g_len[B_];

// ---------------- helpers ----------------------------------------------------
__device__ __forceinline__ float sig_fast(float x) {
    return __fdividef(1.0f, 1.0f + __expf(-x));
}
__device__ __forceinline__ float tanh_fast(float x) {
    const float e = __expf(-2.0f * x);
    return __fdividef(1.0f - e, 1.0f + e);
}
__device__ __forceinline__ float to_tf32(float x) {
    float r;
    asm("cvt.rna.tf32.f32 %0, %1;" : "=f"(r) : "f"(x));
    return r;
}
// D(16x8,f32) += A(16x8,tf32,row) * B(8x8,tf32,col); operands pre-rounded.
__device__ __forceinline__ void mma_tf32(float d[4], const unsigned a[4],
                                         const unsigned b[2]) {
    asm volatile(
        "mma.sync.aligned.m16n8k8.row.col.f32.tf32.tf32.f32 "
        "{%0,%1,%2,%3}, {%4,%5,%6,%7}, {%8,%9}, {%0,%1,%2,%3};"
        : "+f"(d[0]), "+f"(d[1]), "+f"(d[2]), "+f"(d[3])
        : "r"(a[0]), "r"(a[1]), "r"(a[2]), "r"(a[3]), "r"(b[0]), "r"(b[1]));
}
__device__ __forceinline__ void cp16(float* dst_smem, const float* src) {
    const unsigned d = (unsigned)__cvta_generic_to_shared(dst_smem);
    asm volatile("cp.async.cg.shared.global [%0], [%1], 16;"
                 :: "r"(d), "l"(src) : "memory");
}
#define CP_COMMIT() asm volatile("cp.async.commit_group;" ::: "memory")

// ---------------- combined init: dtype detect + lengths + h/bar zero ----------
__global__ void combo_init_kernel(const void* x, const void* lengths) {
    const int tid = threadIdx.x;
    __shared__ int s64;
    if (tid == 0) {
        const int* xi = (const int*)x;
        int flag = 1;
        for (int i = 1; i <= 16; ++i)
            if (xi[2 * i + 1] != 0) flag = 0;
        g_is64 = flag;
        s64 = flag;
        g_barF = 0u;
        g_barB = 0u;
    }
    __syncthreads();
    if (tid < B_) {
        int l = s64 ? (int)((const long long*)lengths)[tid]
                    : ((const int*)lengths)[tid];
        g_len[tid] = l;
    }
    const int n = 2 * B_ * H_;
    for (int i = tid; i < n; i += blockDim.x) {
        ((float*)g_hF)[i] = 0.0f;
        ((float*)g_hB)[i] = 0.0f;
    }
}

// ---------------- mid init (between layers) -----------------------------------
__global__ void mid_init_kernel() {
    int i = blockIdx.x * blockDim.x + threadIdx.x;
    const int n = 2 * B_ * H_;
    if (i < n) {
        ((float*)g_hF)[i] = 0.0f;
        ((float*)g_hB)[i] = 0.0f;
    }
    if (i == 0) { g_barF = 0u; g_barB = 0u; }
}

// ---------------- single-launch weight rounding (all 4 w_ih) ------------------
__global__ void round_all_kernel(const float* __restrict__ f1,
                                 const float* __restrict__ b1,
                                 const float* __restrict__ f2,
                                 const float* __restrict__ b2) {
    const int i = blockIdx.x * blockDim.x + threadIdx.x;   // float4 index
    const int S1 = 2048 * 256 / 4;          // 131072
    const int S2 = 2048 * 1024 / 4;         // 524288
    const float4* src;
    int local;
    if (i < S1)                { src = (const float4*)f1; local = i; }
    else if (i < 2 * S1)       { src = (const float4*)b1; local = i - S1; }
    else if (i < 2 * S1 + S2)  { src = (const float4*)f2; local = i - 2 * S1; }
    else                       { src = (const float4*)b2; local = i - 2 * S1 - S2; }
    float4 v = src[local];
    v.x = to_tf32(v.x); v.y = to_tf32(v.y);
    v.z = to_tf32(v.z); v.w = to_tf32(v.w);
    ((float4*)g_wrnd)[i] = v;
}

// ---------------- embedding gather (tf32-rounded) -----------------------------
__global__ void gather_kernel(const void* x, const float* __restrict__ emb) {
    const int row = blockIdx.x;
    long long idx = g_is64 ? ((const long long*)x)[row]
                           : (long long)((const int*)x)[row];
    float4 v = ((const float4*)(emb + (size_t)idx * E_))[threadIdx.x];
    v.x = to_tf32(v.x); v.y = to_tf32(v.y);
    v.z = to_tf32(v.z); v.w = to_tf32(v.w);
    ((float4*)(g_e + (size_t)row * E_))[threadIdx.x] = v;
}

// ---------------- tf32 MMA pre-GEMM: C[M,2048] = A[M,K] @ W[2048,K]^T + bias --
// CTA tile 128x128, 8 warps (2m x 4n of 64x32), k-chunk 16, 3-stage cp.async.
__global__ void __launch_bounds__(256, 2)
mma_pre_gemm(const float* __restrict__ A, const float* __restrict__ W,
             const float* __restrict__ bias, float* __restrict__ C, int K) {
    __shared__ __align__(16) float sA[3][128 * PRE_S];
    __shared__ __align__(16) float sB[3][128 * PRE_S];
    const int tid  = threadIdx.x;
    const int lane = tid & 31;
    const int wrp  = tid >> 5;
    const int tg   = lane >> 2;
    const int tk   = lane & 3;
    const int bm = blockIdx.y * 128;
    const int bn = blockIdx.x * 128;
    const int wm = (wrp >> 2) * 64;
    const int wn = (wrp & 3) * 32;

    const int lrow = tid >> 1;
    const int lk   = (tid & 1) * 8;

    float d[4][4][4];
#pragma unroll
    for (int mi = 0; mi < 4; ++mi)
#pragma unroll
        for (int ni = 0; ni < 4; ++ni)
#pragma unroll
            for (int q = 0; q < 4; ++q) d[mi][ni][q] = 0.0f;

    const int NT = K >> 4;

    auto issue_stage = [&](int buf, int kt) {
        const float* Ap = A + (size_t)(bm + lrow) * K + kt * 16 + lk;
        const float* Bp = W + (size_t)(bn + lrow) * K + kt * 16 + lk;
        cp16(&sA[buf][lrow * PRE_S + lk], Ap);
        cp16(&sA[buf][lrow * PRE_S + lk + 4], Ap + 4);
        cp16(&sB[buf][lrow * PRE_S + lk], Bp);
        cp16(&sB[buf][lrow * PRE_S + lk + 4], Bp + 4);
        CP_COMMIT();
    };

    issue_stage(0, 0);
    issue_stage(1, 1);

    for (int i = 0; i < NT; ++i) {
        if (i + 1 < NT)
            asm volatile("cp.async.wait_group 1;" ::: "memory");
        else
            asm volatile("cp.async.wait_group 0;" ::: "memory");
        __syncthreads();
        const int buf = i % 3;
        const unsigned* uA = (const unsigned*)sA[buf];
        const unsigned* uB = (const unsigned*)sB[buf];
#pragma unroll
        for (int ks8 = 0; ks8 < 2; ++ks8) {
            const int kb = ks8 * 8;
            unsigned af[4][4], bf[4][2];
#pragma unroll
            for (int mi = 0; mi < 4; ++mi) {
                const int rb = wm + mi * 16;
                af[mi][0] = uA[(rb + tg) * PRE_S + kb + tk];
                af[mi][1] = uA[(rb + tg + 8) * PRE_S + kb + tk];
                af[mi][2] = uA[(rb + tg) * PRE_S + kb + tk + 4];
                af[mi][3] = uA[(rb + tg + 8) * PRE_S + kb + tk + 4];
            }
#pragma unroll
            for (int ni = 0; ni < 4; ++ni) {
                const int nb = wn + ni * 8;
                bf[ni][0] = uB[(nb + tg) * PRE_S + kb + tk];
                bf[ni][1] = uB[(nb + tg) * PRE_S + kb + tk + 4];
            }
#pragma unroll
            for (int mi = 0; mi < 4; ++mi)
#pragma unroll
                for (int ni = 0; ni < 4; ++ni)
                    mma_tf32(d[mi][ni], af[mi], bf[ni]);
        }
        if (i + 2 < NT) issue_stage((i + 2) % 3, i + 2);
    }

#pragma unroll
    for (int mi = 0; mi < 4; ++mi) {
        const int r0 = bm + wm + mi * 16 + tg;
#pragma unroll
        for (int ni = 0; ni < 4; ++ni) {
            const int col = bn + wn + ni * 8 + tk * 2;
            const float2 bb = *(const float2*)&bias[col];
            *(float2*)&C[(size_t)r0 * H4_ + col] =
                make_float2(d[mi][ni][0] + bb.x, d[mi][ni][1] + bb.y);
            *(float2*)&C[(size_t)(r0 + 8) * H4_ + col] =
                make_float2(d[mi][ni][2] + bb.x, d[mi][ni][3] + bb.y);
        }
    }
}

// ---------------- persistent BiLSTM layer (R14 + poll-overlapped outBuf) ------
// 128 CTAs x 512 threads. bx>>6 = dir, bx&63 = column group. W_hh slice
// resident in smem (RNA-rounded tf32, swizzled). Per step: warp-pair ks
// cp.async-stages its own 16KB h k-slice, pair named-barrier, MMA (pre[t+1]
// prefetch hoisted above it), pair barrier, pair-local partial dump, block
// sync, reduce+EW, h store, sync; tid0 arrives at the single-atomic barrier
// (R9 proven form) and polls while ALL OTHER threads store outBuf and swap
// prefetch regs inside the poll window; last step skips the barrier.
__global__ void __launch_bounds__(512, 1)
lstm_layer_kernel(const float* __restrict__ preF, const float* __restrict__ preB,
                  const float* __restrict__ whF, const float* __restrict__ whB,
                  float* __restrict__ outBuf) {
    extern __shared__ __align__(16) float smem_[];
    float* sW = smem_;                          // [512][32] swizzled tf32
    float* sH = smem_ + 512 * 32;               // [512][64]; slice ks reused as sGp
    int* sLen = (int*)(smem_ + 512 * 32 + 512 * 64);
    unsigned* uW = (unsigned*)sW;
    unsigned* uH = (unsigned*)sH;

    const int tid  = threadIdx.x;
    const int bx   = blockIdx.x;
    const int dir  = bx >> 6;
    const int cg   = bx & 63;
    const int lane = tid & 31;
    const int wrp  = tid >> 5;
    const int tg   = lane >> 2;
    const int tk   = lane & 3;
    const int ks   = wrp >> 1;                  // K slice 0..7 (64 k each)
    const int ns   = wrp & 1;                   // N half (16 gate cols)

    const float* __restrict__ pre = dir ? preB : preF;
    const float* __restrict__ W   = dir ? whB : whF;
    float* hbase = dir ? &g_hB[0][0] : &g_hF[0][0];
    unsigned* barp = dir ? &g_barB : &g_barF;

    if (tid < B_) sLen[tid] = g_len[tid];
    // W_hh slice -> smem [k][n] swizzled, RNA-rounded (coalesced in k)
    for (int idx = tid; idx < 32 * 512; idx += 512) {
        const int j = idx >> 9;                 // gate col 0..31
        const int k = idx & 511;
        const int gcol = (j >> 3) * 512 + cg * 8 + (j & 7);
        sW[k * 32 + (j ^ ((k & 3) << 3))] = to_tf32(W[(size_t)gcol * H_ + k]);
    }
    __syncthreads();

    // elementwise mapping: 1 elem/thread
    const int row = tid >> 3;                   // 0..63
    const int hj  = tid & 7;
    const int len = sLen[row];

    float creg = 0.f, hreg = 0.f;

    // prefetch pre for t=0 (always valid: len >= 1)
    float p[4], pn[4];
    {
        const int pos = dir ? (len - 1) : 0;
        const size_t pb = ((size_t)row * T_ + pos) * H4_ + cg * 8 + hj;
#pragma unroll
        for (int g = 0; g < 4; ++g) p[g] = __ldg(&pre[pb + g * 512]);
    }

    for (int t = 0; t < T_; ++t) {
        // ---- stage OWN k-slice via cp.async; pair-sync via named barrier ----
        {
            const float* hsrc = hbase + (size_t)(t & 1) * (H_ * B_);
            const int cbase = ks * 1024 + ns * 512;   // 16B-chunk index base
#pragma unroll
            for (int i = 0; i < 16; ++i) {
                const int idx = cbase + i * 32 + lane;
                const int k  = idx >> 4;
                const int mq = (idx & 15) << 2;
                cp16(&sH[k * 64 + (mq ^ ((k & 3) << 3))], hsrc + idx * 4);
            }
            CP_COMMIT();
            asm volatile("cp.async.wait_group 0;" ::: "memory");
            asm volatile("bar.sync %0, 64;" :: "r"(1 + ks) : "memory");
        }

        // ---- prefetch pre for t+1 (hidden under MMA + barriers) ----
        if (t + 1 < T_) {
            const int tn = t + 1;
            const bool v = (tn < len);
            const int pos = dir ? (v ? (len - 1 - tn) : tn) : tn;
            const size_t pb = ((size_t)row * T_ + pos) * H4_ + cg * 8 + hj;
#pragma unroll
            for (int g = 0; g < 4; ++g) pn[g] = __ldg(&pre[pb + g * 512]);
        }

        // ---- MMA: warp (ks, ns): m64 n16 k64 ----
        float d[4][2][4];
#pragma unroll
        for (int mi = 0; mi < 4; ++mi)
#pragma unroll
            for (int ni = 0; ni < 2; ++ni)
#pragma unroll
                for (int q = 0; q < 4; ++q) d[mi][ni][q] = 0.0f;

#pragma unroll
        for (int kc = 0; kc < 8; ++kc) {
            const int kb = ks * 64 + kc * 8;
            const int sw = tk << 3;
            unsigned af[4][4], bf[2][2];
#pragma unroll
            for (int mi = 0; mi < 4; ++mi) {
                const int rb = mi * 16;
                af[mi][0] = uH[(kb + tk) * 64 + ((rb + tg) ^ sw)];
                af[mi][1] = uH[(kb + tk) * 64 + ((rb + tg + 8) ^ sw)];
                af[mi][2] = uH[(kb + tk + 4) * 64 + ((rb + tg) ^ sw)];
                af[mi][3] = uH[(kb + tk + 4) * 64 + ((rb + tg + 8) ^ sw)];
            }
#pragma unroll
            for (int ni = 0; ni < 2; ++ni) {
                const int nb = ns * 16 + ni * 8;
                bf[ni][0] = uW[(kb + tk) * 32 + ((nb + tg) ^ sw)];
                bf[ni][1] = uW[(kb + tk + 4) * 32 + ((nb + tg) ^ sw)];
            }
#pragma unroll
            for (int mi = 0; mi < 4; ++mi)
#pragma unroll
                for (int ni = 0; ni < 2; ++ni)
                    mma_tf32(d[mi][ni], af[mi], bf[ni]);
        }
        // pair done reading slice ks -> safe to overwrite with own partials
        asm volatile("bar.sync %0, 64;" :: "r"(1 + ks) : "memory");

        // ---- dump split-K partials into OWN slice region (pair-local) ----
        {
            float* g = sH + ks * 4096;          // [32][GP_J] fits in 4096 floats
#pragma unroll
            for (int mi = 0; mi < 4; ++mi) {
                const int mb = mi * 16 + tg;
#pragma unroll
                for (int ni = 0; ni < 2; ++ni) {
                    const int nb = ns * 16 + ni * 8 + tk * 2;
                    g[nb * GP_J + mb]           = d[mi][ni][0];
                    g[(nb + 1) * GP_J + mb]     = d[mi][ni][1];
                    g[nb * GP_J + mb + 8]       = d[mi][ni][2];
                    g[(nb + 1) * GP_J + mb + 8] = d[mi][ni][3];
                }
            }
        }
        __syncthreads();

        // ---- reduce + elementwise (1 elem/thread) ----
        float* hnext = hbase + (size_t)((t + 1) & 1) * (H_ * B_);
        const bool valid = (t < len);
        const int pos = dir ? (valid ? (len - 1 - t) : t) : t;
        float hn;
        {
            float gi = 0.f, gf = 0.f, gg = 0.f, go = 0.f;
#pragma unroll
            for (int w = 0; w < 8; ++w) {
                const float* gp = sH + w * 4096 + row;
                gi += gp[(hj)      * GP_J];
                gf += gp[(8 + hj)  * GP_J];
                gg += gp[(16 + hj) * GP_J];
                go += gp[(24 + hj) * GP_J];
            }
            gi += p[0]; gf += p[1]; gg += p[2]; go += p[3];

            const float iv = sig_fast(gi);
            const float fv = sig_fast(gf);
            const float gv = tanh_fast(gg);
            const float ov = sig_fast(go);
            const float cn = fv * creg + iv * gv;
            hn = ov * tanh_fast(cn);
            if (valid) { creg = cn; hreg = hn; }

            __stcg(&hnext[(cg * 8 + hj) * 64 + row], to_tf32(hreg));
        }

        if (t + 1 == T_) {   // last step: h(T) has no consumer; skip barrier
            outBuf[((size_t)row * T_ + pos) * (2 * H_) + dir * H_ + cg * 8 + hj] =
                valid ? to_tf32(hn) : 0.0f;
            break;
        }

        // ---- all h stores in this CTA done ----
        __syncthreads();

        // ---- tid0: arrive + poll; everyone else overlaps outBuf + p-swap ----
        if (tid == 0) {
            __threadfence();
            atomicAdd(barp, 1u);
        }
        outBuf[((size_t)row * T_ + pos) * (2 * H_) + dir * H_ + cg * 8 + hj] =
            valid ? to_tf32(hn) : 0.0f;
#pragma unroll
        for (int g = 0; g < 4; ++g) p[g] = pn[g];
        if (tid == 0) {
            const unsigned tgt = (unsigned)(t + 1) * 64u;
            unsigned v;
            do {
                asm volatile("ld.relaxed.gpu.global.u32 %0, [%1];"
                             : "=r"(v) : "l"(barp));
            } while (v < tgt);
            asm volatile("fence.acq_rel.gpu;" ::: "memory");
        }
        __syncthreads();
    }
}

// ---------------- classifier --------------------------------------------------
__global__ void __launch_bounds__(256, 1)
classifier_kernel(const float* __restrict__ clsW, const float* __restrict__ clsB,
                  float* __restrict__ out) {
    __shared__ __align__(16) float sX[8][1028];
    const int tid = threadIdx.x;
    const size_t r0 = (size_t)blockIdx.x * 8;
    const float* src = g_out2 + r0 * (2 * H_);
    for (int i = tid; i < 8 * 256; i += 256) {
        const int rr = i >> 8;
        const int kk = (i & 255) * 4;
        *(float4*)&sX[rr][kk] = *(const float4*)(src + (size_t)rr * 1024 + kk);
    }
    __syncthreads();
    for (int e = tid; e < 8 * TAGS_; e += 256) {
        const int r = e & 7;
        const int c = e >> 3;
        const float* w = clsW + (size_t)c * 1024;
        float s0 = 0.f, s1 = 0.f, s2 = 0.f, s3 = 0.f;
#pragma unroll 8
        for (int k = 0; k < 1024; k += 4) {
            const float4 a = *(const float4*)&sX[r][k];
            const float4 b = __ldg((const float4*)(w + k));
            s0 += a.x * b.x; s1 += a.y * b.y; s2 += a.z * b.z; s3 += a.w * b.w;
        }
        out[(r0 + r) * TAGS_ + c] = s0 + s1 + s2 + s3 + clsB[c];
    }
}

// ---------------- host launcher -----------------------------------------------
extern "C" void kernel_launch(void* const* d_in, const int* in_sizes, int n_in,
                              void* d_out, int out_size) {
    (void)in_sizes; (void)n_in; (void)out_size;
    const void*  x        = d_in[0];
    const void*  lengths  = d_in[1];
    const float* emb      = (const float*)d_in[2];
    const float* w_ih_f1  = (const float*)d_in[3];
    const float* w_hh_f1  = (const float*)d_in[4];
    const float* b_f1     = (const float*)d_in[5];
    const float* w_ih_b1  = (const float*)d_in[6];
    const float* w_hh_b1  = (const float*)d_in[7];
    const float* b_b1     = (const float*)d_in[8];
    const float* w_ih_f2  = (const float*)d_in[9];
    const float* w_hh_f2  = (const float*)d_in[10];
    const float* b_f2     = (const float*)d_in[11];
    const float* w_ih_b2  = (const float*)d_in[12];
    const float* w_hh_b2  = (const float*)d_in[13];
    const float* b_b2     = (const float*)d_in[14];
    const float* cls_w    = (const float*)d_in[15];
    const float* cls_b    = (const float*)d_in[16];
    float* out = (float*)d_out;

    float *pE, *pPF, *pPB, *pO1, *pO2, *pWR;
    cudaGetSymbolAddress((void**)&pE,  g_e);
    cudaGetSymbolAddress((void**)&pPF, g_preF);
    cudaGetSymbolAddress((void**)&pPB, g_preB);
    cudaGetSymbolAddress((void**)&pO1, g_out1);
    cudaGetSymbolAddress((void**)&pO2, g_out2);
    cudaGetSymbolAddress((void**)&pWR, g_wrnd);

    cudaFuncSetAttribute(lstm_layer_kernel,
                         cudaFuncAttributeMaxDynamicSharedMemorySize,
                         LSTM_SMEM_BYTES);

    const int M = B_ * T_;
    const dim3 pre_grid(H4_ / 128, M / 128);    // (16, 128)

    combo_init_kernel<<<1, 1024>>>(x, lengths);
    gather_kernel<<<M, 64>>>(x, emb);
    round_all_kernel<<<WR_TOTAL / 4 / 256, 256>>>(w_ih_f1, w_ih_b1,
                                                  w_ih_f2, w_ih_b2);
    mma_pre_gemm<<<pre_grid, 256>>>(pE, pWR + WR_F1, b_f1, pPF, E_);
    mma_pre_gemm<<<pre_grid, 256>>>(pE, pWR + WR_B1, b_b1, pPB, E_);
    lstm_layer_kernel<<<128, 512, LSTM_SMEM_BYTES>>>(pPF, pPB, w_hh_f1, w_hh_b1,
                                                     pO1);

    mid_init_kernel<<<256, 256>>>();

    mma_pre_gemm<<<pre_grid, 256>>>(pO1, pWR + WR_F2, b_f2, pPF, 2 * H_);
    mma_pre_gemm<<<pre_grid, 256>>>(pO1, pWR + WR_B2, b_b2, pPB, 2 * H_);
    lstm_layer_kernel<<<128, 512, LSTM_SMEM_BYTES>>>(pPF, pPB, w_hh_f2, w_hh_b2,
                                                     pO2);

    classifier_kernel<<<M / 8, 256>>>(cls_w, cls_b, out);
}

// round 16
// speedup vs baseline: 1.0300x; 1.0300x over previous
#include <cuda_runtime.h>
#include <cstdint>
#include <cstdio>

#define B_    64
#define T_    256
#define E_    256
#define H_    512
#define H4_   2048
#define TAGS_ 50

#define GP_J  68                         // split-K partial col stride (reduce CF)
#define PRE_S 20                         // pre-GEMM smem row stride (floats)
// lstm smem: sW 512*32 + sH 512*64 + sLen(64) + sPerm(64) + sCnt(256)
#define LSTM_SMEM_FLOATS (512 * 32 + 512 * 64 + 64 + 64 + 256)
#define LSTM_SMEM_BYTES  (LSTM_SMEM_FLOATS * 4)

// rounded-weight scratch offsets (floats)
#define WR_F1 0
#define WR_B1 (2048 * 256)
#define WR_F2 (2 * 2048 * 256)
#define WR_B2 (2 * 2048 * 256 + 2048 * 1024)
#define WR_TOTAL (2 * 2048 * 256 + 2 * 2048 * 1024)

// ---------------- scratch ----------------------------------------------------
__device__ float g_e[B_ * T_ * E_];
__device__ float g_preF[(size_t)B_ * T_ * H4_];
__device__ float g_preB[(size_t)B_ * T_ * H4_];
__device__ float g_out1[(size_t)B_ * T_ * 2 * H_];
__device__ float g_out2[(size_t)B_ * T_ * 2 * H_];
__device__ float g_hF[2][H_ * B_];          // [k][sorted row], tf32-rounded
__device__ float g_hB[2][H_ * B_];
__device__ float g_wrnd[WR_TOTAL];          // RNA-rounded w_ih weights
__device__ __align__(128) unsigned g_barF;
__device__ __align__(128) unsigned g_barB;
__device__ int g_is64;
__device__ int g_perm[B_];                  // sorted rank -> original row
__device__ int g_slen[B_];                  // lengths, descending

// ---------------- helpers ----------------------------------------------------
__device__ __forceinline__ float sig_fast(float x) {
    return __fdividef(1.0f, 1.0f + __expf(-x));
}
__device__ __forceinline__ float tanh_fast(float x) {
    const float e = __expf(-2.0f * x);
    return __fdividef(1.0f - e, 1.0f + e);
}
__device__ __forceinline__ float to_tf32(float x) {
    float r;
    asm("cvt.rna.tf32.f32 %0, %1;" : "=f"(r) : "f"(x));
    return r;
}
// D(16x8,f32) += A(16x8,tf32,row) * B(8x8,tf32,col); operands pre-rounded.
__device__ __forceinline__ void mma_tf32(float d[4], const unsigned a[4],
                                         const unsigned b[2]) {
    asm volatile(
        "mma.sync.aligned.m16n8k8.row.col.f32.tf32.tf32.f32 "
        "{%0,%1,%2,%3}, {%4,%5,%6,%7}, {%8,%9}, {%0,%1,%2,%3};"
        : "+f"(d[0]), "+f"(d[1]), "+f"(d[2]), "+f"(d[3])
        : "r"(a[0]), "r"(a[1]), "r"(a[2]), "r"(a[3]), "r"(b[0]), "r"(b[1]));
}
__device__ __forceinline__ void cp16(float* dst_smem, const float* src) {
    const unsigned d = (unsigned)__cvta_generic_to_shared(dst_smem);
    asm volatile("cp.async.cg.shared.global [%0], [%1], 16;"
                 :: "r"(d), "l"(src) : "memory");
}
#define CP_COMMIT() asm volatile("cp.async.commit_group;" ::: "memory")

// ---------------- combined init: detect + length sort + h/bar zero ------------
__global__ void combo_init_kernel(const void* x, const void* lengths) {
    const int tid = threadIdx.x;
    __shared__ int s64;
    __shared__ int sl[B_];
    if (tid == 0) {
        const int* xi = (const int*)x;
        int flag = 1;
        for (int i = 1; i <= 16; ++i)
            if (xi[2 * i + 1] != 0) flag = 0;
        g_is64 = flag;
        s64 = flag;
        g_barF = 0u;
        g_barB = 0u;
    }
    __syncthreads();
    if (tid < B_) {
        int l = s64 ? (int)((const long long*)lengths)[tid]
                    : ((const int*)lengths)[tid];
        sl[tid] = l;
    }
    __syncthreads();
    if (tid < B_) {
        const int lr = sl[tid];
        int rank = 0;
        for (int j = 0; j < B_; ++j) {
            const int lj = sl[j];
            rank += (lj > lr) || (lj == lr && j < tid);
        }
        g_perm[rank] = tid;
        g_slen[rank] = lr;
    }
    const int n = 2 * B_ * H_;
    for (int i = tid; i < n; i += blockDim.x) {
        ((float*)g_hF)[i] = 0.0f;
        ((float*)g_hB)[i] = 0.0f;
    }
}

// ---------------- mid init (between layers) -----------------------------------
__global__ void mid_init_kernel() {
    int i = blockIdx.x * blockDim.x + threadIdx.x;
    const int n = 2 * B_ * H_;
    if (i < n) {
        ((float*)g_hF)[i] = 0.0f;
        ((float*)g_hB)[i] = 0.0f;
    }
    if (i == 0) { g_barF = 0u; g_barB = 0u; }
}

// ---------------- zero out1/out2 (padding positions must be exactly 0) --------
__global__ void zero_out_kernel() {
    const float4 z = make_float4(0.f, 0.f, 0.f, 0.f);
    const size_t N = (size_t)B_ * T_ * 2 * H_ / 4;
    for (size_t i = (size_t)blockIdx.x * blockDim.x + threadIdx.x; i < N;
         i += (size_t)gridDim.x * blockDim.x) {
        ((float4*)g_out1)[i] = z;
        ((float4*)g_out2)[i] = z;
    }
}

// ---------------- single-launch weight rounding (all 4 w_ih) ------------------
__global__ void round_all_kernel(const float* __restrict__ f1,
                                 const float* __restrict__ b1,
                                 const float* __restrict__ f2,
                                 const float* __restrict__ b2) {
    const int i = blockIdx.x * blockDim.x + threadIdx.x;   // float4 index
    const int S1 = 2048 * 256 / 4;
    const int S2 = 2048 * 1024 / 4;
    const float4* src;
    int local;
    if (i < S1)                { src = (const float4*)f1; local = i; }
    else if (i < 2 * S1)       { src = (const float4*)b1; local = i - S1; }
    else if (i < 2 * S1 + S2)  { src = (const float4*)f2; local = i - 2 * S1; }
    else                       { src = (const float4*)b2; local = i - 2 * S1 - S2; }
    float4 v = src[local];
    v.x = to_tf32(v.x); v.y = to_tf32(v.y);
    v.z = to_tf32(v.z); v.w = to_tf32(v.w);
    ((float4*)g_wrnd)[i] = v;
}

// ---------------- embedding gather (tf32-rounded) -----------------------------
__global__ void gather_kernel(const void* x, const float* __restrict__ emb) {
    const int row = blockIdx.x;
    long long idx = g_is64 ? ((const long long*)x)[row]
                           : (long long)((const int*)x)[row];
    float4 v = ((const float4*)(emb + (size_t)idx * E_))[threadIdx.x];
    v.x = to_tf32(v.x); v.y = to_tf32(v.y);
    v.z = to_tf32(v.z); v.w = to_tf32(v.w);
    ((float4*)(g_e + (size_t)row * E_))[threadIdx.x] = v;
}

// ---------------- tf32 MMA pre-GEMM: C[M,2048] = A[M,K] @ W[2048,K]^T + bias --
__global__ void __launch_bounds__(256, 2)
mma_pre_gemm(const float* __restrict__ A, const float* __restrict__ W,
             const float* __restrict__ bias, float* __restrict__ C, int K) {
    __shared__ __align__(16) float sA[3][128 * PRE_S];
    __shared__ __align__(16) float sB[3][128 * PRE_S];
    const int tid  = threadIdx.x;
    const int lane = tid & 31;
    const int wrp  = tid >> 5;
    const int tg   = lane >> 2;
    const int tk   = lane & 3;
    const int bm = blockIdx.y * 128;
    const int bn = blockIdx.x * 128;
    const int wm = (wrp >> 2) * 64;
    const int wn = (wrp & 3) * 32;

    const int lrow = tid >> 1;
    const int lk   = (tid & 1) * 8;

    float d[4][4][4];
#pragma unroll
    for (int mi = 0; mi < 4; ++mi)
#pragma unroll
        for (int ni = 0; ni < 4; ++ni)
#pragma unroll
            for (int q = 0; q < 4; ++q) d[mi][ni][q] = 0.0f;

    const int NT = K >> 4;

    auto issue_stage = [&](int buf, int kt) {
        const float* Ap = A + (size_t)(bm + lrow) * K + kt * 16 + lk;
        const float* Bp = W + (size_t)(bn + lrow) * K + kt * 16 + lk;
        cp16(&sA[buf][lrow * PRE_S + lk], Ap);
        cp16(&sA[buf][lrow * PRE_S + lk + 4], Ap + 4);
        cp16(&sB[buf][lrow * PRE_S + lk], Bp);
        cp16(&sB[buf][lrow * PRE_S + lk + 4], Bp + 4);
        CP_COMMIT();
    };

    issue_stage(0, 0);
    issue_stage(1, 1);

    for (int i = 0; i < NT; ++i) {
        if (i + 1 < NT)
            asm volatile("cp.async.wait_group 1;" ::: "memory");
        else
            asm volatile("cp.async.wait_group 0;" ::: "memory");
        __syncthreads();
        const int buf = i % 3;
        const unsigned* uA = (const unsigned*)sA[buf];
        const unsigned* uB = (const unsigned*)sB[buf];
#pragma unroll
        for (int ks8 = 0; ks8 < 2; ++ks8) {
            const int kb = ks8 * 8;
            unsigned af[4][4], bf[4][2];
#pragma unroll
            for (int mi = 0; mi < 4; ++mi) {
                const int rb = wm + mi * 16;
                af[mi][0] = uA[(rb + tg) * PRE_S + kb + tk];
                af[mi][1] = uA[(rb + tg + 8) * PRE_S + kb + tk];
                af[mi][2] = uA[(rb + tg) * PRE_S + kb + tk + 4];
                af[mi][3] = uA[(rb + tg + 8) * PRE_S + kb + tk + 4];
            }
#pragma unroll
            for (int ni = 0; ni < 4; ++ni) {
                const int nb = wn + ni * 8;
                bf[ni][0] = uB[(nb + tg) * PRE_S + kb + tk];
                bf[ni][1] = uB[(nb + tg) * PRE_S + kb + tk + 4];
            }
#pragma unroll
            for (int mi = 0; mi < 4; ++mi)
#pragma unroll
                for (int ni = 0; ni < 4; ++ni)
                    mma_tf32(d[mi][ni], af[mi], bf[ni]);
        }
        if (i + 2 < NT) issue_stage((i + 2) % 3, i + 2);
    }

#pragma unroll
    for (int mi = 0; mi < 4; ++mi) {
        const int r0 = bm + wm + mi * 16 + tg;
#pragma unroll
        for (int ni = 0; ni < 4; ++ni) {
            const int col = bn + wn + ni * 8 + tk * 2;
            const float2 bb = *(const float2*)&bias[col];
            *(float2*)&C[(size_t)r0 * H4_ + col] =
                make_float2(d[mi][ni][0] + bb.x, d[mi][ni][1] + bb.y);
            *(float2*)&C[(size_t)(r0 + 8) * H4_ + col] =
                make_float2(d[mi][ni][2] + bb.x, d[mi][ni][3] + bb.y);
        }
    }
}

// ---------------- persistent BiLSTM layer (length-sorted, shrinking m) --------
// Rows sorted by length descending (compute space); alive rows at step t are
// the prefix [0, m_t), identical across CTAs/directions. MMA mi-blocks, dump,
// reduce, EW, h/out stores all bounded by m_t. pre/outBuf indexed via perm.
// Sync structure = proven R9/R15 single-atomic rendezvous.
__global__ void __launch_bounds__(512, 1)
lstm_layer_kernel(const float* __restrict__ preF, const float* __restrict__ preB,
                  const float* __restrict__ whF, const float* __restrict__ whB,
                  float* __restrict__ outBuf) {
    extern __shared__ __align__(16) float smem_[];
    float* sW = smem_;                          // [512][32] swizzled tf32
    float* sH = smem_ + 512 * 32;               // [512][64]; slice ks reused as sGp
    int* sLen  = (int*)(smem_ + 512 * 32 + 512 * 64);
    int* sPerm = sLen + 64;
    int* sCnt  = sPerm + 64;                    // m_t per step
    unsigned* uW = (unsigned*)sW;
    unsigned* uH = (unsigned*)sH;

    const int tid  = threadIdx.x;
    const int bx   = blockIdx.x;
    const int dir  = bx >> 6;
    const int cg   = bx & 63;
    const int lane = tid & 31;
    const int wrp  = tid >> 5;
    const int tg   = lane >> 2;
    const int tk   = lane & 3;
    const int ks   = wrp >> 1;                  // K slice 0..7 (64 k each)
    const int ns   = wrp & 1;                   // N half (16 gate cols)

    const float* __restrict__ pre = dir ? preB : preF;
    const float* __restrict__ W   = dir ? whB : whF;
    float* hbase = dir ? &g_hB[0][0] : &g_hF[0][0];
    unsigned* barp = dir ? &g_barB : &g_barF;

    if (tid < B_) { sLen[tid] = g_slen[tid]; sPerm[tid] = g_perm[tid]; }
    // W_hh slice -> smem [k][n] swizzled, RNA-rounded (coalesced in k)
    for (int idx = tid; idx < 32 * 512; idx += 512) {
        const int j = idx >> 9;                 // gate col 0..31
        const int k = idx & 511;
        const int gcol = (j >> 3) * 512 + cg * 8 + (j & 7);
        sW[k * 32 + (j ^ ((k & 3) << 3))] = to_tf32(W[(size_t)gcol * H_ + k]);
    }
    __syncthreads();
    // alive-count table: m_t = #rows with len > t (rows sorted descending)
    for (int t = tid; t < T_; t += 512) {
        int m = 0;
#pragma unroll 8
        for (int r = 0; r < B_; ++r) m += (sLen[r] > t);
        sCnt[t] = m;
    }
    __syncthreads();

    // elementwise mapping: 1 elem/thread (sorted row space)
    const int row  = tid >> 3;                  // 0..63
    const int hj   = tid & 7;
    const int len  = sLen[row];
    const int orow = sPerm[row];

    float creg = 0.f, hreg = 0.f;

    // prefetch pre for t=0 (all rows alive: len >= 1)
    float p[4], pn[4];
    {
        const int pos = dir ? (len - 1) : 0;
        const size_t pb = ((size_t)orow * T_ + pos) * H4_ + cg * 8 + hj;
#pragma unroll
        for (int g = 0; g < 4; ++g) p[g] = __ldg(&pre[pb + g * 512]);
    }

    for (int t = 0; t < T_; ++t) {
        const int mt = sCnt[t];
        const int mb = (mt + 15) >> 4;          // alive 16-row blocks (1..4)

        // ---- stage OWN k-slice via cp.async; pair-sync via named barrier ----
        {
            const float* hsrc = hbase + (size_t)(t & 1) * (H_ * B_);
            const int cbase = ks * 1024 + ns * 512;
#pragma unroll
            for (int i = 0; i < 16; ++i) {
                const int idx = cbase + i * 32 + lane;
                const int k  = idx >> 4;
                const int mq = (idx & 15) << 2;
                cp16(&sH[k * 64 + (mq ^ ((k & 3) << 3))], hsrc + idx * 4);
            }
            CP_COMMIT();
            asm volatile("cp.async.wait_group 0;" ::: "memory");
            asm volatile("bar.sync %0, 64;" :: "r"(1 + ks) : "memory");
        }

        // ---- prefetch pre for t+1 (only if this row is alive then) ----
        if (t + 1 < len) {
            const int tn = t + 1;
            const int pos = dir ? (len - 1 - tn) : tn;
            const size_t pb = ((size_t)orow * T_ + pos) * H4_ + cg * 8 + hj;
#pragma unroll
            for (int g = 0; g < 4; ++g) pn[g] = __ldg(&pre[pb + g * 512]);
        }

        // ---- MMA: warp (ks, ns): m = mb*16, n16, k64 ----
        float d[4][2][4];
#pragma unroll
        for (int mi = 0; mi < 4; ++mi)
#pragma unroll
            for (int ni = 0; ni < 2; ++ni)
#pragma unroll
                for (int q = 0; q < 4; ++q) d[mi][ni][q] = 0.0f;

#pragma unroll
        for (int kc = 0; kc < 8; ++kc) {
            const int kb = ks * 64 + kc * 8;
            const int sw = tk << 3;
            unsigned bf[2][2];
#pragma unroll
            for (int ni = 0; ni < 2; ++ni) {
                const int nb = ns * 16 + ni * 8;
                bf[ni][0] = uW[(kb + tk) * 32 + ((nb + tg) ^ sw)];
                bf[ni][1] = uW[(kb + tk + 4) * 32 + ((nb + tg) ^ sw)];
            }
#pragma unroll
            for (int mi = 0; mi < 4; ++mi) {
                if (mi < mb) {
                    const int rb = mi * 16;
                    unsigned af[4];
                    af[0] = uH[(kb + tk) * 64 + ((rb + tg) ^ sw)];
                    af[1] = uH[(kb + tk) * 64 + ((rb + tg + 8) ^ sw)];
                    af[2] = uH[(kb + tk + 4) * 64 + ((rb + tg) ^ sw)];
                    af[3] = uH[(kb + tk + 4) * 64 + ((rb + tg + 8) ^ sw)];
#pragma unroll
                    for (int ni = 0; ni < 2; ++ni)
                        mma_tf32(d[mi][ni], af, bf[ni]);
                }
            }
        }
        // pair done reading slice ks -> safe to overwrite with own partials
        asm volatile("bar.sync %0, 64;" :: "r"(1 + ks) : "memory");

        // ---- dump split-K partials into OWN slice region (alive blocks) ----
        {
            float* g = sH + ks * 4096;          // [32][GP_J]
#pragma unroll
            for (int mi = 0; mi < 4; ++mi) {
                if (mi < mb) {
                    const int mbs = mi * 16 + tg;
#pragma unroll
                    for (int ni = 0; ni < 2; ++ni) {
                        const int nb = ns * 16 + ni * 8 + tk * 2;
                        g[nb * GP_J + mbs]           = d[mi][ni][0];
                        g[(nb + 1) * GP_J + mbs]     = d[mi][ni][1];
                        g[nb * GP_J + mbs + 8]       = d[mi][ni][2];
                        g[(nb + 1) * GP_J + mbs + 8] = d[mi][ni][3];
                    }
                }
            }
        }
        __syncthreads();

        // ---- reduce + elementwise (alive rows only) ----
        float* hnext = hbase + (size_t)((t + 1) & 1) * (H_ * B_);
        float hn = 0.f;
        const int pos = dir ? (len - 1 - t) : t;
        if (row < mt) {
            float gi = 0.f, gf = 0.f, gg = 0.f, go = 0.f;
#pragma unroll
            for (int w = 0; w < 8; ++w) {
                const float* gp = sH + w * 4096 + row;
                gi += gp[(hj)      * GP_J];
                gf += gp[(8 + hj)  * GP_J];
                gg += gp[(16 + hj) * GP_J];
                go += gp[(24 + hj) * GP_J];
            }
            gi += p[0]; gf += p[1]; gg += p[2]; go += p[3];

            const float iv = sig_fast(gi);
            const float fv = sig_fast(gf);
            const float gv = tanh_fast(gg);
            const float ov = sig_fast(go);
            const float cn = fv * creg + iv * gv;
            hn = ov * tanh_fast(cn);
            creg = cn; hreg = hn;

            __stcg(&hnext[(cg * 8 + hj) * 64 + row], to_tf32(hreg));
        }

        if (t + 1 == T_) {   // last step: no consumer of h(T); skip barrier
            if (row < mt)
                outBuf[((size_t)orow * T_ + pos) * (2 * H_) + dir * H_ +
                       cg * 8 + hj] = to_tf32(hn);
            break;
        }

        // ---- all h stores in this CTA done ----
        __syncthreads();

        // ---- tid0: arrive; others overlap outBuf + p-swap; tid0 polls ----
        if (tid == 0) {
            __threadfence();
            atomicAdd(barp, 1u);
        }
        if (row < mt)
            outBuf[((size_t)orow * T_ + pos) * (2 * H_) + dir * H_ +
                   cg * 8 + hj] = to_tf32(hn);
#pragma unroll
        for (int g = 0; g < 4; ++g) p[g] = pn[g];
        if (tid == 0) {
            const unsigned tgt = (unsigned)(t + 1) * 64u;
            unsigned v;
            do {
                asm volatile("ld.relaxed.gpu.global.u32 %0, [%1];"
                             : "=r"(v) : "l"(barp));
            } while (v < tgt);
            asm volatile("fence.acq_rel.gpu;" ::: "memory");
        }
        __syncthreads();
    }
}

// ---------------- classifier --------------------------------------------------
__global__ void __launch_bounds__(256, 1)
classifier_kernel(const float* __restrict__ clsW, const float* __restrict__ clsB,
                  float* __restrict__ out) {
    __shared__ __align__(16) float sX[8][1028];
    const int tid = threadIdx.x;
    const size_t r0 = (size_t)blockIdx.x * 8;
    const float* src = g_out2 + r0 * (2 * H_);
    for (int i = tid; i < 8 * 256; i += 256) {
        const int rr = i >> 8;
        const int kk = (i & 255) * 4;
        *(float4*)&sX[rr][kk] = *(const float4*)(src + (size_t)rr * 1024 + kk);
    }
    __syncthreads();
    for (int e = tid; e < 8 * TAGS_; e += 256) {
        const int r = e & 7;
        const int c = e >> 3;
        const float* w = clsW + (size_t)c * 1024;
        float s0 = 0.f, s1 = 0.f, s2 = 0.f, s3 = 0.f;
#pragma unroll 8
        for (int k = 0; k < 1024; k += 4) {
            const float4 a = *(const float4*)&sX[r][k];
            const float4 b = __ldg((const float4*)(w + k));
            s0 += a.x * b.x; s1 += a.y * b.y; s2 += a.z * b.z; s3 += a.w * b.w;
        }
        out[(r0 + r) * TAGS_ + c] = s0 + s1 + s2 + s3 + clsB[c];
    }
}

// ---------------- host launcher -----------------------------------------------
extern "C" void kernel_launch(void* const* d_in, const int* in_sizes, int n_in,
                              void* d_out, int out_size) {
    (void)in_sizes; (void)n_in; (void)out_size;
    const void*  x        = d_in[0];
    const void*  lengths  = d_in[1];
    const float* emb      = (const float*)d_in[2];
    const float* w_ih_f1  = (const float*)d_in[3];
    const float* w_hh_f1  = (const float*)d_in[4];
    const float* b_f1     = (const float*)d_in[5];
    const float* w_ih_b1  = (const float*)d_in[6];
    const float* w_hh_b1  = (const float*)d_in[7];
    const float* b_b1     = (const float*)d_in[8];
    const float* w_ih_f2  = (const float*)d_in[9];
    const float* w_hh_f2  = (const float*)d_in[10];
    const float* b_f2     = (const float*)d_in[11];
    const float* w_ih_b2  = (const float*)d_in[12];
    const float* w_hh_b2  = (const float*)d_in[13];
    const float* b_b2     = (const float*)d_in[14];
    const float* cls_w    = (const float*)d_in[15];
    const float* cls_b    = (const float*)d_in[16];
    float* out = (float*)d_out;

    float *pE, *pPF, *pPB, *pO1, *pO2, *pWR;
    cudaGetSymbolAddress((void**)&pE,  g_e);
    cudaGetSymbolAddress((void**)&pPF, g_preF);
    cudaGetSymbolAddress((void**)&pPB, g_preB);
    cudaGetSymbolAddress((void**)&pO1, g_out1);
    cudaGetSymbolAddress((void**)&pO2, g_out2);
    cudaGetSymbolAddress((void**)&pWR, g_wrnd);

    cudaFuncSetAttribute(lstm_layer_kernel,
                         cudaFuncAttributeMaxDynamicSharedMemorySize,
                         LSTM_SMEM_BYTES);

    const int M = B_ * T_;
    const dim3 pre_grid(H4_ / 128, M / 128);    // (16, 128)

    combo_init_kernel<<<1, 1024>>>(x, lengths);
    zero_out_kernel<<<4096, 256>>>();
    gather_kernel<<<M, 64>>>(x, emb);
    round_all_kernel<<<WR_TOTAL / 4 / 256, 256>>>(w_ih_f1, w_ih_b1,
                                                  w_ih_f2, w_ih_b2);
    mma_pre_gemm<<<pre_grid, 256>>>(pE, pWR + WR_F1, b_f1, pPF, E_);
    mma_pre_gemm<<<pre_grid, 256>>>(pE, pWR + WR_B1, b_b1, pPB, E_);
    lstm_layer_kernel<<<128, 512, LSTM_SMEM_BYTES>>>(pPF, pPB, w_hh_f1, w_hh_b1,
                                                     pO1);

    mid_init_kernel<<<256, 256>>>();

    mma_pre_gemm<<<pre_grid, 256>>>(pO1, pWR + WR_F2, b_f2, pPF, 2 * H_);
    mma_pre_gemm<<<pre_grid, 256>>>(pO1, pWR + WR_B2, b_b2, pPB, 2 * H_);
    lstm_layer_kernel<<<128, 512, LSTM_SMEM_BYTES>>>(pPF, pPB, w_hh_f2, w_hh_b2,
                                                     pO2);

    classifier_kernel<<<M / 8, 256>>>(cls_w, cls_b, out);
}

// round 17
// speedup vs baseline: 1.1655x; 1.1315x over previous
#include <cuda_runtime.h>
#include <cstdint>
#include <cstdio>

#define B_    64
#define T_    256
#define E_    256
#define H_    512
#define H4_   2048
#define TAGS_ 50

#define GP_J  68                         // split-K partial col stride (reduce CF)
#define PRE_S 20                         // pre-GEMM smem row stride (floats)
// lstm smem: sW 512*32 + sH 512*64 + sLen(64) + sPerm(64) + sCnt(256)
#define LSTM_SMEM_FLOATS (512 * 32 + 512 * 64 + 64 + 64 + 256)
#define LSTM_SMEM_BYTES  (LSTM_SMEM_FLOATS * 4)

// rounded-weight scratch offsets (floats)
#define WR_F1 0
#define WR_B1 (2048 * 256)
#define WR_F2 (2 * 2048 * 256)
#define WR_B2 (2 * 2048 * 256 + 2048 * 1024)
#define WR_TOTAL (2 * 2048 * 256 + 2 * 2048 * 1024)

// ---------------- scratch ----------------------------------------------------
__device__ float g_e[B_ * T_ * E_];
__device__ float g_preF[(size_t)B_ * T_ * H4_];
__device__ float g_preB[(size_t)B_ * T_ * H4_];
__device__ float g_out1[(size_t)B_ * T_ * 2 * H_];
__device__ float g_out2[(size_t)B_ * T_ * 2 * H_];
__device__ float g_hF[2][H_ * B_];          // [k][sorted row], tf32-rounded
__device__ float g_hB[2][H_ * B_];
__device__ float g_wrnd[WR_TOTAL];          // RNA-rounded w_ih weights
__device__ __align__(128) unsigned g_barF;
__device__ __align__(128) unsigned g_barB;
__device__ int g_is64;
__device__ int g_perm[B_];                  // sorted rank -> original row
__device__ int g_slen[B_];                  // lengths, descending
__device__ int g_lenO[B_];                  // lengths, original order

// ---------------- helpers ----------------------------------------------------
__device__ __forceinline__ float sig_fast(float x) {
    return __fdividef(1.0f, 1.0f + __expf(-x));
}
__device__ __forceinline__ float tanh_fast(float x) {
    const float e = __expf(-2.0f * x);
    return __fdividef(1.0f - e, 1.0f + e);
}
__device__ __forceinline__ float to_tf32(float x) {
    float r;
    asm("cvt.rna.tf32.f32 %0, %1;" : "=f"(r) : "f"(x));
    return r;
}
// D(16x8,f32) += A(16x8,tf32,row) * B(8x8,tf32,col); operands pre-rounded.
__device__ __forceinline__ void mma_tf32(float d[4], const unsigned a[4],
                                         const unsigned b[2]) {
    asm volatile(
        "mma.sync.aligned.m16n8k8.row.col.f32.tf32.tf32.f32 "
        "{%0,%1,%2,%3}, {%4,%5,%6,%7}, {%8,%9}, {%0,%1,%2,%3};"
        : "+f"(d[0]), "+f"(d[1]), "+f"(d[2]), "+f"(d[3])
        : "r"(a[0]), "r"(a[1]), "r"(a[2]), "r"(a[3]), "r"(b[0]), "r"(b[1]));
}
__device__ __forceinline__ void cp16(float* dst_smem, const float* src) {
    const unsigned d = (unsigned)__cvta_generic_to_shared(dst_smem);
    asm volatile("cp.async.cg.shared.global [%0], [%1], 16;"
                 :: "r"(d), "l"(src) : "memory");
}
#define CP_COMMIT() asm volatile("cp.async.commit_group;" ::: "memory")

// ---------------- combined init: detect + length sort + h/bar zero ------------
__global__ void combo_init_kernel(const void* x, const void* lengths) {
    const int tid = threadIdx.x;
    __shared__ int s64;
    __shared__ int sl[B_];
    if (tid == 0) {
        const int* xi = (const int*)x;
        int flag = 1;
        for (int i = 1; i <= 16; ++i)
            if (xi[2 * i + 1] != 0) flag = 0;
        g_is64 = flag;
        s64 = flag;
        g_barF = 0u;
        g_barB = 0u;
    }
    __syncthreads();
    if (tid < B_) {
        int l = s64 ? (int)((const long long*)lengths)[tid]
                    : ((const int*)lengths)[tid];
        sl[tid] = l;
        g_lenO[tid] = l;
    }
    __syncthreads();
    if (tid < B_) {
        const int lr = sl[tid];
        int rank = 0;
        for (int j = 0; j < B_; ++j) {
            const int lj = sl[j];
            rank += (lj > lr) || (lj == lr && j < tid);
        }
        g_perm[rank] = tid;
        g_slen[rank] = lr;
    }
    const int n = 2 * B_ * H_;
    for (int i = tid; i < n; i += blockDim.x) {
        ((float*)g_hF)[i] = 0.0f;
        ((float*)g_hB)[i] = 0.0f;
    }
}

// ---------------- mid init (between layers) -----------------------------------
__global__ void mid_init_kernel() {
    int i = blockIdx.x * blockDim.x + threadIdx.x;
    const int n = 2 * B_ * H_;
    if (i < n) {
        ((float*)g_hF)[i] = 0.0f;
        ((float*)g_hB)[i] = 0.0f;
    }
    if (i == 0) { g_barF = 0u; g_barB = 0u; }
}

// ---------------- zero out1/out2 (padding positions must be exactly 0) --------
__global__ void zero_out_kernel() {
    const float4 z = make_float4(0.f, 0.f, 0.f, 0.f);
    const size_t N = (size_t)B_ * T_ * 2 * H_ / 4;
    for (size_t i = (size_t)blockIdx.x * blockDim.x + threadIdx.x; i < N;
         i += (size_t)gridDim.x * blockDim.x) {
        ((float4*)g_out1)[i] = z;
        ((float4*)g_out2)[i] = z;
    }
}

// ---------------- single-launch weight rounding (all 4 w_ih) ------------------
__global__ void round_all_kernel(const float* __restrict__ f1,
                                 const float* __restrict__ b1,
                                 const float* __restrict__ f2,
                                 const float* __restrict__ b2) {
    const int i = blockIdx.x * blockDim.x + threadIdx.x;   // float4 index
    const int S1 = 2048 * 256 / 4;
    const int S2 = 2048 * 1024 / 4;
    const float4* src;
    int local;
    if (i < S1)                { src = (const float4*)f1; local = i; }
    else if (i < 2 * S1)       { src = (const float4*)b1; local = i - S1; }
    else if (i < 2 * S1 + S2)  { src = (const float4*)f2; local = i - 2 * S1; }
    else                       { src = (const float4*)b2; local = i - 2 * S1 - S2; }
    float4 v = src[local];
    v.x = to_tf32(v.x); v.y = to_tf32(v.y);
    v.z = to_tf32(v.z); v.w = to_tf32(v.w);
    ((float4*)g_wrnd)[i] = v;
}

// ---------------- embedding gather (tf32-rounded) -----------------------------
__global__ void gather_kernel(const void* x, const float* __restrict__ emb) {
    const int row = blockIdx.x;
    long long idx = g_is64 ? ((const long long*)x)[row]
                           : (long long)((const int*)x)[row];
    float4 v = ((const float4*)(emb + (size_t)idx * E_))[threadIdx.x];
    v.x = to_tf32(v.x); v.y = to_tf32(v.y);
    v.z = to_tf32(v.z); v.w = to_tf32(v.w);
    ((float4*)(g_e + (size_t)row * E_))[threadIdx.x] = v;
}

// ---------------- tf32 MMA pre-GEMM (dead-tile skip) ---------------------------
// C[M,2048] = A[M,K] @ W[2048,K]^T + bias. CTA tile 128x128. Both directions
// read pre only at pos < len, so a tile whose 128 time-positions all satisfy
// t >= len[b] is dead -> early return.
__global__ void __launch_bounds__(256, 2)
mma_pre_gemm(const float* __restrict__ A, const float* __restrict__ W,
             const float* __restrict__ bias, float* __restrict__ C, int K) {
    const int bm = blockIdx.y * 128;
    {   // dead-tile skip: rows [bm, bm+128) are (b = bm/256, t in [ts, ts+128))
        const int b  = bm >> 8;
        const int ts = bm & 255;
        if (g_lenO[b] <= ts) return;
    }
    __shared__ __align__(16) float sA[3][128 * PRE_S];
    __shared__ __align__(16) float sB[3][128 * PRE_S];
    const int tid  = threadIdx.x;
    const int lane = tid & 31;
    const int wrp  = tid >> 5;
    const int tg   = lane >> 2;
    const int tk   = lane & 3;
    const int bn = blockIdx.x * 128;
    const int wm = (wrp >> 2) * 64;
    const int wn = (wrp & 3) * 32;

    const int lrow = tid >> 1;
    const int lk   = (tid & 1) * 8;

    float d[4][4][4];
#pragma unroll
    for (int mi = 0; mi < 4; ++mi)
#pragma unroll
        for (int ni = 0; ni < 4; ++ni)
#pragma unroll
            for (int q = 0; q < 4; ++q) d[mi][ni][q] = 0.0f;

    const int NT = K >> 4;

    auto issue_stage = [&](int buf, int kt) {
        const float* Ap = A + (size_t)(bm + lrow) * K + kt * 16 + lk;
        const float* Bp = W + (size_t)(bn + lrow) * K + kt * 16 + lk;
        cp16(&sA[buf][lrow * PRE_S + lk], Ap);
        cp16(&sA[buf][lrow * PRE_S + lk + 4], Ap + 4);
        cp16(&sB[buf][lrow * PRE_S + lk], Bp);
        cp16(&sB[buf][lrow * PRE_S + lk + 4], Bp + 4);
        CP_COMMIT();
    };

    issue_stage(0, 0);
    issue_stage(1, 1);

    for (int i = 0; i < NT; ++i) {
        if (i + 1 < NT)
            asm volatile("cp.async.wait_group 1;" ::: "memory");
        else
            asm volatile("cp.async.wait_group 0;" ::: "memory");
        __syncthreads();
        const int buf = i % 3;
        const unsigned* uA = (const unsigned*)sA[buf];
        const unsigned* uB = (const unsigned*)sB[buf];
#pragma unroll
        for (int ks8 = 0; ks8 < 2; ++ks8) {
            const int kb = ks8 * 8;
            unsigned af[4][4], bf[4][2];
#pragma unroll
            for (int mi = 0; mi < 4; ++mi) {
                const int rb = wm + mi * 16;
                af[mi][0] = uA[(rb + tg) * PRE_S + kb + tk];
                af[mi][1] = uA[(rb + tg + 8) * PRE_S + kb + tk];
                af[mi][2] = uA[(rb + tg) * PRE_S + kb + tk + 4];
                af[mi][3] = uA[(rb + tg + 8) * PRE_S + kb + tk + 4];
            }
#pragma unroll
            for (int ni = 0; ni < 4; ++ni) {
                const int nb = wn + ni * 8;
                bf[ni][0] = uB[(nb + tg) * PRE_S + kb + tk];
                bf[ni][1] = uB[(nb + tg) * PRE_S + kb + tk + 4];
            }
#pragma unroll
            for (int mi = 0; mi < 4; ++mi)
#pragma unroll
                for (int ni = 0; ni < 4; ++ni)
                    mma_tf32(d[mi][ni], af[mi], bf[ni]);
        }
        if (i + 2 < NT) issue_stage((i + 2) % 3, i + 2);
    }

#pragma unroll
    for (int mi = 0; mi < 4; ++mi) {
        const int r0 = bm + wm + mi * 16 + tg;
#pragma unroll
        for (int ni = 0; ni < 4; ++ni) {
            const int col = bn + wn + ni * 8 + tk * 2;
            const float2 bb = *(const float2*)&bias[col];
            *(float2*)&C[(size_t)r0 * H4_ + col] =
                make_float2(d[mi][ni][0] + bb.x, d[mi][ni][1] + bb.y);
            *(float2*)&C[(size_t)(r0 + 8) * H4_ + col] =
                make_float2(d[mi][ni][2] + bb.x, d[mi][ni][3] + bb.y);
        }
    }
}

// ---------------- persistent BiLSTM layer (length-sorted, shrinking m+stage) --
// Rows sorted by length descending; alive rows at step t are prefix [0, m_t).
// Staging lane -> fixed 4-row group ((lane&15)*4): dead lanes skip their
// cp.asyncs entirely, so staged bytes scale with m_t. MMA/dump/reduce/EW all
// m_t-bounded. Sync = proven single-atomic rendezvous.
__global__ void __launch_bounds__(512, 1)
lstm_layer_kernel(const float* __restrict__ preF, const float* __restrict__ preB,
                  const float* __restrict__ whF, const float* __restrict__ whB,
                  float* __restrict__ outBuf) {
    extern __shared__ __align__(16) float smem_[];
    float* sW = smem_;                          // [512][32] swizzled tf32
    float* sH = smem_ + 512 * 32;               // [512][64]; slice ks reused as sGp
    int* sLen  = (int*)(smem_ + 512 * 32 + 512 * 64);
    int* sPerm = sLen + 64;
    int* sCnt  = sPerm + 64;                    // m_t per step
    unsigned* uW = (unsigned*)sW;
    unsigned* uH = (unsigned*)sH;

    const int tid  = threadIdx.x;
    const int bx   = blockIdx.x;
    const int dir  = bx >> 6;
    const int cg   = bx & 63;
    const int lane = tid & 31;
    const int wrp  = tid >> 5;
    const int tg   = lane >> 2;
    const int tk   = lane & 3;
    const int ks   = wrp >> 1;                  // K slice 0..7 (64 k each)
    const int ns   = wrp & 1;                   // N half (16 gate cols)

    const float* __restrict__ pre = dir ? preB : preF;
    const float* __restrict__ W   = dir ? whB : whF;
    float* hbase = dir ? &g_hB[0][0] : &g_hF[0][0];
    unsigned* barp = dir ? &g_barB : &g_barF;

    if (tid < B_) { sLen[tid] = g_slen[tid]; sPerm[tid] = g_perm[tid]; }
    // W_hh slice -> smem [k][n] swizzled, RNA-rounded (coalesced in k)
    for (int idx = tid; idx < 32 * 512; idx += 512) {
        const int j = idx >> 9;                 // gate col 0..31
        const int k = idx & 511;
        const int gcol = (j >> 3) * 512 + cg * 8 + (j & 7);
        sW[k * 32 + (j ^ ((k & 3) << 3))] = to_tf32(W[(size_t)gcol * H_ + k]);
    }
    __syncthreads();
    // alive-count table: m_t = #rows with len > t (rows sorted descending)
    for (int t = tid; t < T_; t += 512) {
        int m = 0;
#pragma unroll 8
        for (int r = 0; r < B_; ++r) m += (sLen[r] > t);
        sCnt[t] = m;
    }
    __syncthreads();

    // staging: this lane always copies row group [smq, smq+4)
    const int smq = (lane & 15) << 2;

    // elementwise mapping: 1 elem/thread (sorted row space)
    const int row  = tid >> 3;                  // 0..63
    const int hj   = tid & 7;
    const int len  = sLen[row];
    const int orow = sPerm[row];

    float creg = 0.f, hreg = 0.f;

    // prefetch pre for t=0 (all rows alive: len >= 1)
    float p[4], pn[4];
    {
        const int pos = dir ? (len - 1) : 0;
        const size_t pb = ((size_t)orow * T_ + pos) * H4_ + cg * 8 + hj;
#pragma unroll
        for (int g = 0; g < 4; ++g) p[g] = __ldg(&pre[pb + g * 512]);
    }

    for (int t = 0; t < T_; ++t) {
        const int mt = sCnt[t];
        const int mb = (mt + 15) >> 4;          // alive 16-row blocks (1..4)

        // ---- stage OWN k-slice, alive row-groups only ----
        {
            const float* hsrc = hbase + (size_t)(t & 1) * (H_ * B_);
            const int cbase = ks * 1024 + ns * 512;
            if (smq < mt) {
#pragma unroll
                for (int i = 0; i < 16; ++i) {
                    const int idx = cbase + i * 32 + lane;
                    const int k  = idx >> 4;
                    cp16(&sH[k * 64 + (smq ^ ((k & 3) << 3))], hsrc + idx * 4);
                }
            }
            CP_COMMIT();
            asm volatile("cp.async.wait_group 0;" ::: "memory");
            asm volatile("bar.sync %0, 64;" :: "r"(1 + ks) : "memory");
        }

        // ---- prefetch pre for t+1 (only if this row is alive then) ----
        if (t + 1 < len) {
            const int tn = t + 1;
            const int pos = dir ? (len - 1 - tn) : tn;
            const size_t pb = ((size_t)orow * T_ + pos) * H4_ + cg * 8 + hj;
#pragma unroll
            for (int g = 0; g < 4; ++g) pn[g] = __ldg(&pre[pb + g * 512]);
        }

        // ---- MMA: warp (ks, ns): m = mb*16, n16, k64 ----
        float d[4][2][4];
#pragma unroll
        for (int mi = 0; mi < 4; ++mi)
#pragma unroll
            for (int ni = 0; ni < 2; ++ni)
#pragma unroll
                for (int q = 0; q < 4; ++q) d[mi][ni][q] = 0.0f;

#pragma unroll
        for (int kc = 0; kc < 8; ++kc) {
            const int kb = ks * 64 + kc * 8;
            const int sw = tk << 3;
            unsigned bf[2][2];
#pragma unroll
            for (int ni = 0; ni < 2; ++ni) {
                const int nb = ns * 16 + ni * 8;
                bf[ni][0] = uW[(kb + tk) * 32 + ((nb + tg) ^ sw)];
                bf[ni][1] = uW[(kb + tk + 4) * 32 + ((nb + tg) ^ sw)];
            }
#pragma unroll
            for (int mi = 0; mi < 4; ++mi) {
                if (mi < mb) {
                    const int rb = mi * 16;
                    unsigned af[4];
                    af[0] = uH[(kb + tk) * 64 + ((rb + tg) ^ sw)];
                    af[1] = uH[(kb + tk) * 64 + ((rb + tg + 8) ^ sw)];
                    af[2] = uH[(kb + tk + 4) * 64 + ((rb + tg) ^ sw)];
                    af[3] = uH[(kb + tk + 4) * 64 + ((rb + tg + 8) ^ sw)];
#pragma unroll
                    for (int ni = 0; ni < 2; ++ni)
                        mma_tf32(d[mi][ni], af, bf[ni]);
                }
            }
        }
        // pair done reading slice ks -> safe to overwrite with own partials
        asm volatile("bar.sync %0, 64;" :: "r"(1 + ks) : "memory");

        // ---- dump split-K partials into OWN slice region (alive blocks) ----
        {
            float* g = sH + ks * 4096;          // [32][GP_J]
#pragma unroll
            for (int mi = 0; mi < 4; ++mi) {
                if (mi < mb) {
                    const int mbs = mi * 16 + tg;
#pragma unroll
                    for (int ni = 0; ni < 2; ++ni) {
                        const int nb = ns * 16 + ni * 8 + tk * 2;
                        g[nb * GP_J + mbs]           = d[mi][ni][0];
                        g[(nb + 1) * GP_J + mbs]     = d[mi][ni][1];
                        g[nb * GP_J + mbs + 8]       = d[mi][ni][2];
                        g[(nb + 1) * GP_J + mbs + 8] = d[mi][ni][3];
                    }
                }
            }
        }
        __syncthreads();

        // ---- reduce + elementwise (alive rows only) ----
        float* hnext = hbase + (size_t)((t + 1) & 1) * (H_ * B_);
        float hn = 0.f;
        const int pos = dir ? (len - 1 - t) : t;
        if (row < mt) {
            float gi = 0.f, gf = 0.f, gg = 0.f, go = 0.f;
#pragma unroll
            for (int w = 0; w < 8; ++w) {
                const float* gp = sH + w * 4096 + row;
                gi += gp[(hj)      * GP_J];
                gf += gp[(8 + hj)  * GP_J];
                gg += gp[(16 + hj) * GP_J];
                go += gp[(24 + hj) * GP_J];
            }
            gi += p[0]; gf += p[1]; gg += p[2]; go += p[3];

            const float iv = sig_fast(gi);
            const float fv = sig_fast(gf);
            const float gv = tanh_fast(gg);
            const float ov = sig_fast(go);
            const float cn = fv * creg + iv * gv;
            hn = ov * tanh_fast(cn);
            creg = cn; hreg = hn;

            __stcg(&hnext[(cg * 8 + hj) * 64 + row], to_tf32(hreg));
        }

        if (t + 1 == T_) {   // last step: no consumer of h(T); skip barrier
            if (row < mt)
                outBuf[((size_t)orow * T_ + pos) * (2 * H_) + dir * H_ +
                       cg * 8 + hj] = to_tf32(hn);
            break;
        }

        // ---- all h stores in this CTA done ----
        __syncthreads();

        // ---- tid0: arrive; others overlap outBuf + p-swap; tid0 polls ----
        if (tid == 0) {
            __threadfence();
            atomicAdd(barp, 1u);
        }
        if (row < mt)
            outBuf[((size_t)orow * T_ + pos) * (2 * H_) + dir * H_ +
                   cg * 8 + hj] = to_tf32(hn);
#pragma unroll
        for (int g = 0; g < 4; ++g) p[g] = pn[g];
        if (tid == 0) {
            const unsigned tgt = (unsigned)(t + 1) * 64u;
            unsigned v;
            do {
                asm volatile("ld.relaxed.gpu.global.u32 %0, [%1];"
                             : "=r"(v) : "l"(barp));
            } while (v < tgt);
            asm volatile("fence.acq_rel.gpu;" ::: "memory");
        }
        __syncthreads();
    }
}

// ---------------- classifier --------------------------------------------------
__global__ void __launch_bounds__(256, 1)
classifier_kernel(const float* __restrict__ clsW, const float* __restrict__ clsB,
                  float* __restrict__ out) {
    __shared__ __align__(16) float sX[8][1028];
    const int tid = threadIdx.x;
    const size_t r0 = (size_t)blockIdx.x * 8;
    const float* src = g_out2 + r0 * (2 * H_);
    for (int i = tid; i < 8 * 256; i += 256) {
        const int rr = i >> 8;
        const int kk = (i & 255) * 4;
        *(float4*)&sX[rr][kk] = *(const float4*)(src + (size_t)rr * 1024 + kk);
    }
    __syncthreads();
    for (int e = tid; e < 8 * TAGS_; e += 256) {
        const int r = e & 7;
        const int c = e >> 3;
        const float* w = clsW + (size_t)c * 1024;
        float s0 = 0.f, s1 = 0.f, s2 = 0.f, s3 = 0.f;
#pragma unroll 8
        for (int k = 0; k < 1024; k += 4) {
            const float4 a = *(const float4*)&sX[r][k];
            const float4 b = __ldg((const float4*)(w + k));
            s0 += a.x * b.x; s1 += a.y * b.y; s2 += a.z * b.z; s3 += a.w * b.w;
        }
        out[(r0 + r) * TAGS_ + c] = s0 + s1 + s2 + s3 + clsB[c];
    }
}

// ---------------- host launcher -----------------------------------------------
extern "C" void kernel_launch(void* const* d_in, const int* in_sizes, int n_in,
                              void* d_out, int out_size) {
    (void)in_sizes; (void)n_in; (void)out_size;
    const void*  x        = d_in[0];
    const void*  lengths  = d_in[1];
    const float* emb      = (const float*)d_in[2];
    const float* w_ih_f1  = (const float*)d_in[3];
    const float* w_hh_f1  = (const float*)d_in[4];
    const float* b_f1     = (const float*)d_in[5];
    const float* w_ih_b1  = (const float*)d_in[6];
    const float* w_hh_b1  = (const float*)d_in[7];
    const float* b_b1     = (const float*)d_in[8];
    const float* w_ih_f2  = (const float*)d_in[9];
    const float* w_hh_f2  = (const float*)d_in[10];
    const float* b_f2     = (const float*)d_in[11];
    const float* w_ih_b2  = (const float*)d_in[12];
    const float* w_hh_b2  = (const float*)d_in[13];
    const float* b_b2     = (const float*)d_in[14];
    const float* cls_w    = (const float*)d_in[15];
    const float* cls_b    = (const float*)d_in[16];
    float* out = (float*)d_out;

    float *pE, *pPF, *pPB, *pO1, *pO2, *pWR;
    cudaGetSymbolAddress((void**)&pE,  g_e);
    cudaGetSymbolAddress((void**)&pPF, g_preF);
    cudaGetSymbolAddress((void**)&pPB, g_preB);
    cudaGetSymbolAddress((void**)&pO1, g_out1);
    cudaGetSymbolAddress((void**)&pO2, g_out2);
    cudaGetSymbolAddress((void**)&pWR, g_wrnd);

    cudaFuncSetAttribute(lstm_layer_kernel,
                         cudaFuncAttributeMaxDynamicSharedMemorySize,
                         LSTM_SMEM_BYTES);

    const int M = B_ * T_;
    const dim3 pre_grid(H4_ / 128, M / 128);    // (16, 128)

    combo_init_kernel<<<1, 1024>>>(x, lengths);
    zero_out_kernel<<<4096, 256>>>();
    gather_kernel<<<M, 64>>>(x, emb);
    round_all_kernel<<<WR_TOTAL / 4 / 256, 256>>>(w_ih_f1, w_ih_b1,
                                                  w_ih_f2, w_ih_b2);
    mma_pre_gemm<<<pre_grid, 256>>>(pE, pWR + WR_F1, b_f1, pPF, E_);
    mma_pre_gemm<<<pre_grid, 256>>>(pE, pWR + WR_B1, b_b1, pPB, E_);
    lstm_layer_kernel<<<128, 512, LSTM_SMEM_BYTES>>>(pPF, pPB, w_hh_f1, w_hh_b1,
                                                     pO1);

    mid_init_kernel<<<256, 256>>>();

    mma_pre_gemm<<<pre_grid, 256>>>(pO1, pWR + WR_F2, b_f2, pPF, 2 * H_);
    mma_pre_gemm<<<pre_grid, 256>>>(pO1, pWR + WR_B2, b_b2, pPB, 2 * H_);
    lstm_layer_kernel<<<128, 512, LSTM_SMEM_BYTES>>>(pPF, pPB, w_hh_f2, w_hh_b2,
                                                     pO2);

    classifier_kernel<<<M / 8, 256>>>(cls_w, cls_b, out);
}